// round 5
// baseline (speedup 1.0000x reference)
#include <cuda_runtime.h>

#define TPB   256
#define KDIM  4096
#define KD4   1024
#define ND4   1024
#define RANK  8

typedef unsigned long long u64;

// BP[rp][k] = { B[k][2rp], B[k][2rp+1] }   (4 x 4096 u64 = 128 KB)
__device__ u64   BP_g[4 * KDIM];
// t = 2 * (x @ B)   [16384 rows x 8]  = 512 KB
__device__ float t_g[16384 * RANK];

__global__ void pack_B_kernel(const float* __restrict__ B)
{
    int o = blockIdx.x * blockDim.x + threadIdx.x;   // 0..16383
    int rp = o >> 12;
    int k  = o & (KDIM - 1);
    BP_g[o] = ((const u64*)B)[k * 4 + rp];
}

__device__ __forceinline__ u64 pack2(float lo, float hi) {
    u64 d; asm("mov.b64 %0, {%1,%2};" : "=l"(d) : "f"(lo), "f"(hi)); return d;
}
__device__ __forceinline__ void fma2(u64 &d, u64 a, u64 b) {
    asm("fma.rn.f32x2 %0, %1, %2, %0;" : "+l"(d) : "l"(a), "l"(b));
}
__device__ __forceinline__ u64 add2(u64 a, u64 b) {
    u64 d; asm("add.rn.f32x2 %0, %1, %2;" : "=l"(d) : "l"(a), "l"(b)); return d;
}
__device__ __forceinline__ float2 unpack2(u64 v) {
    float2 f; asm("mov.b64 {%0,%1}, %2;" : "=f"(f.x), "=f"(f.y) : "l"(v)); return f;
}

// ================= K1: t = 2 * x @ B  (pure read stream) =================
// 4 rows per warp, 8 warps => 32 rows/CTA, grid 512, occ 3 target.
__global__ __launch_bounds__(TPB, 3)
void lora_k1_kernel(const float* __restrict__ x)
{
    const int lane = threadIdx.x & 31;
    const int warp = threadIdx.x >> 5;
    const size_t row0 = ((size_t)blockIdx.x * 8 + warp) * 4;

    const float4* __restrict__ xr = (const float4*)x + row0 * KD4;
    const ulonglong2* __restrict__ BP2 = (const ulonglong2*)BP_g;

    u64 acc[4][4];
    #pragma unroll
    for (int m = 0; m < 4; ++m)
        #pragma unroll
        for (int rp = 0; rp < 4; ++rp) acc[m][rp] = 0ull;

    for (int i = 0; i < 32; ++i) {
        const int p = i * 32 + lane;

        // B pairs for this lane's 4 k-values (L1-resident after first touch)
        const ulonglong2 b00 = BP2[0 * 2048 + 2 * p], b01 = BP2[0 * 2048 + 2 * p + 1];
        const ulonglong2 b10 = BP2[1 * 2048 + 2 * p], b11 = BP2[1 * 2048 + 2 * p + 1];
        const ulonglong2 b20 = BP2[2 * 2048 + 2 * p], b21 = BP2[2 * 2048 + 2 * p + 1];
        const ulonglong2 b30 = BP2[3 * 2048 + 2 * p], b31 = BP2[3 * 2048 + 2 * p + 1];

        float4 xv[4];
        #pragma unroll
        for (int m = 0; m < 4; ++m)
            xv[m] = __ldcs(xr + m * KD4 + p);

        #pragma unroll
        for (int m = 0; m < 4; ++m) {
            const u64 xb0 = pack2(xv[m].x, xv[m].x);
            const u64 xb1 = pack2(xv[m].y, xv[m].y);
            const u64 xb2 = pack2(xv[m].z, xv[m].z);
            const u64 xb3 = pack2(xv[m].w, xv[m].w);
            fma2(acc[m][0], xb0, b00.x);  fma2(acc[m][0], xb1, b00.y);
            fma2(acc[m][0], xb2, b01.x);  fma2(acc[m][0], xb3, b01.y);
            fma2(acc[m][1], xb0, b10.x);  fma2(acc[m][1], xb1, b10.y);
            fma2(acc[m][1], xb2, b11.x);  fma2(acc[m][1], xb3, b11.y);
            fma2(acc[m][2], xb0, b20.x);  fma2(acc[m][2], xb1, b20.y);
            fma2(acc[m][2], xb2, b21.x);  fma2(acc[m][2], xb3, b21.y);
            fma2(acc[m][3], xb0, b30.x);  fma2(acc[m][3], xb1, b30.y);
            fma2(acc[m][3], xb2, b31.x);  fma2(acc[m][3], xb3, b31.y);
        }
    }

    #pragma unroll
    for (int s = 16; s; s >>= 1) {
        #pragma unroll
        for (int m = 0; m < 4; ++m)
            #pragma unroll
            for (int rp = 0; rp < 4; ++rp)
                acc[m][rp] = add2(acc[m][rp],
                                  __shfl_xor_sync(0xFFFFFFFFu, acc[m][rp], s));
    }

    if (lane == 0) {
        float4* __restrict__ t4 = (float4*)t_g;
        #pragma unroll
        for (int m = 0; m < 4; ++m) {
            const float2 f0 = unpack2(acc[m][0]);
            const float2 f1 = unpack2(acc[m][1]);
            const float2 f2 = unpack2(acc[m][2]);
            const float2 f3 = unpack2(acc[m][3]);
            t4[(row0 + m) * 2 + 0] = make_float4(2.f*f0.x, 2.f*f0.y, 2.f*f1.x, 2.f*f1.y);
            t4[(row0 + m) * 2 + 1] = make_float4(2.f*f2.x, 2.f*f2.y, 2.f*f3.x, 2.f*f3.y);
        }
    }
}

// ================= K2: out = t @ A  (pure write stream) =================
// 16 rows/CTA, grid 1024.
#define K2_ROWS 16

__global__ __launch_bounds__(TPB)
void lora_k2_kernel(const float* __restrict__ A, float* __restrict__ out)
{
    __shared__ u64 t2_s[K2_ROWS][RANK];   // {t, t} broadcast pairs

    const int tid = threadIdx.x;
    const size_t row0 = (size_t)blockIdx.x * K2_ROWS;

    if (tid < K2_ROWS * RANK) {
        const float v = t_g[row0 * RANK + tid];
        t2_s[tid >> 3][tid & 7] = pack2(v, v);
    }
    __syncthreads();

    const float4* __restrict__ A4 = (const float4*)A;
    float4* __restrict__ out4 = (float4*)out;

    #pragma unroll
    for (int j = 0; j < 4; ++j) {
        const int p = tid + j * TPB;                 // out float4 col (0..1023)
        u64 alo[RANK], ahi[RANK];
        #pragma unroll
        for (int r = 0; r < RANK; ++r) {
            const float4 a = A4[r * ND4 + p];
            alo[r] = pack2(a.x, a.y);
            ahi[r] = pack2(a.z, a.w);
        }

        #pragma unroll 4
        for (int m = 0; m < K2_ROWS; ++m) {
            const ulonglong2* __restrict__ tp2 = (const ulonglong2*)t2_s[m];
            const ulonglong2 t01 = tp2[0];
            const ulonglong2 t23 = tp2[1];
            const ulonglong2 t45 = tp2[2];
            const ulonglong2 t67 = tp2[3];

            u64 olo = 0ull, ohi = 0ull;
            fma2(olo, t01.x, alo[0]);  fma2(ohi, t01.x, ahi[0]);
            fma2(olo, t01.y, alo[1]);  fma2(ohi, t01.y, ahi[1]);
            fma2(olo, t23.x, alo[2]);  fma2(ohi, t23.x, ahi[2]);
            fma2(olo, t23.y, alo[3]);  fma2(ohi, t23.y, ahi[3]);
            fma2(olo, t45.x, alo[4]);  fma2(ohi, t45.x, ahi[4]);
            fma2(olo, t45.y, alo[5]);  fma2(ohi, t45.y, ahi[5]);
            fma2(olo, t67.x, alo[6]);  fma2(ohi, t67.x, ahi[6]);
            fma2(olo, t67.y, alo[7]);  fma2(ohi, t67.y, ahi[7]);

            const float2 f0 = unpack2(olo);
            const float2 f1 = unpack2(ohi);
            __stcs(&out4[(row0 + m) * ND4 + p], make_float4(f0.x, f0.y, f1.x, f1.y));
        }
    }
}

extern "C" void kernel_launch(void* const* d_in, const int* in_sizes, int n_in,
                              void* d_out, int out_size)
{
    const float* x = (const float*)d_in[0];   // [4,4096,4096]
    const float* A = (const float*)d_in[1];   // [8,4096]
    const float* B = (const float*)d_in[2];   // [4096,8]
    float* out = (float*)d_out;               // [4,4096,4096] fp32

    pack_B_kernel<<<(4 * KDIM) / TPB, TPB>>>(B);

    lora_k1_kernel<<<16384 / 32, TPB>>>(x);            // grid 512
    lora_k2_kernel<<<16384 / K2_ROWS, TPB>>>(A, out);  // grid 1024
}

// round 6
// speedup vs baseline: 1.2380x; 1.2380x over previous
#include <cuda_runtime.h>

#define TPB   256
#define KDIM  4096
#define KD4   1024
#define ND4   1024
#define RANK  8
#define ROWS  16            // rows per CTA

typedef unsigned long long u64;

__device__ __forceinline__ u64 pack2(float lo, float hi) {
    u64 d; asm("mov.b64 %0, {%1,%2};" : "=l"(d) : "f"(lo), "f"(hi)); return d;
}
__device__ __forceinline__ void fma2(u64 &d, u64 a, u64 b) {
    asm("fma.rn.f32x2 %0, %1, %2, %0;" : "+l"(d) : "l"(a), "l"(b));
}
__device__ __forceinline__ u64 add2(u64 a, u64 b) {
    u64 d; asm("add.rn.f32x2 %0, %1, %2;" : "=l"(d) : "l"(a), "l"(b)); return d;
}
__device__ __forceinline__ float2 unpack2(u64 v) {
    float2 f; asm("mov.b64 {%0,%1}, %2;" : "=f"(f.x), "=f"(f.y) : "l"(v)); return f;
}

// Fused: t = 2*x@B (warp = 8 rows x 1024-k quarter), then out = t@A.
// B read DIRECTLY (no pack kernel): for float4-k index p, the 16 u64s at
// ((u64*)B)[16p..16p+15] are {B[k][2rp],B[k][2rp+1]} for k=4p..4p+3, rp=0..3.
__global__ __launch_bounds__(TPB, 2)
void lora_v6_kernel(const float* __restrict__ x,
                    const float* __restrict__ A,
                    const float* __restrict__ B,
                    float* __restrict__ out)
{
    __shared__ u64 part_s[4][2][8][4];   // [kq][rowgrp][m][rp]
    __shared__ u64 t2_s[ROWS][RANK];     // {t,t} broadcast pairs

    const int tid  = threadIdx.x;
    const int lane = tid & 31;
    const int warp = tid >> 5;
    const int rg   = warp & 1;           // row group (0..1)
    const int kq   = warp >> 1;          // k quarter (0..3)
    const size_t row0 = (size_t)blockIdx.x * ROWS;

    const float4* __restrict__ x4 = (const float4*)x;
    const float4* __restrict__ A4 = (const float4*)A;
    const ulonglong2* __restrict__ B2 = (const ulonglong2*)B;
    float4* __restrict__ out4 = (float4*)out;

    // ---------------- Phase 1 ----------------
    {
        const float4* __restrict__ xr = x4 + (row0 + rg * 8) * KD4;

        u64 acc[8][4];
        #pragma unroll
        for (int m = 0; m < 8; ++m)
            #pragma unroll
            for (int rp = 0; rp < 4; ++rp) acc[m][rp] = 0ull;

        for (int i = 0; i < 8; ++i) {
            const int p = kq * 256 + i * 32 + lane;     // float4-k index

            const ulonglong2* __restrict__ gB = B2 + (size_t)p * 8;
            const ulonglong2 g0 = gB[0], g1 = gB[1], g2 = gB[2], g3 = gB[3];
            const ulonglong2 g4 = gB[4], g5 = gB[5], g6 = gB[6], g7 = gB[7];

            #pragma unroll
            for (int h = 0; h < 2; ++h) {
                float4 xv[4];
                #pragma unroll
                for (int q = 0; q < 4; ++q)
                    xv[q] = __ldcs(xr + (h * 4 + q) * KD4 + p);

                #pragma unroll
                for (int q = 0; q < 4; ++q) {
                    const int m = h * 4 + q;
                    const u64 xb0 = pack2(xv[q].x, xv[q].x);
                    const u64 xb1 = pack2(xv[q].y, xv[q].y);
                    const u64 xb2 = pack2(xv[q].z, xv[q].z);
                    const u64 xb3 = pack2(xv[q].w, xv[q].w);
                    fma2(acc[m][0], xb0, g0.x);  fma2(acc[m][1], xb0, g0.y);
                    fma2(acc[m][2], xb0, g1.x);  fma2(acc[m][3], xb0, g1.y);
                    fma2(acc[m][0], xb1, g2.x);  fma2(acc[m][1], xb1, g2.y);
                    fma2(acc[m][2], xb1, g3.x);  fma2(acc[m][3], xb1, g3.y);
                    fma2(acc[m][0], xb2, g4.x);  fma2(acc[m][1], xb2, g4.y);
                    fma2(acc[m][2], xb2, g5.x);  fma2(acc[m][3], xb2, g5.y);
                    fma2(acc[m][0], xb3, g6.x);  fma2(acc[m][1], xb3, g6.y);
                    fma2(acc[m][2], xb3, g7.x);  fma2(acc[m][3], xb3, g7.y);
                }
            }
        }

        #pragma unroll
        for (int s = 16; s; s >>= 1) {
            #pragma unroll
            for (int m = 0; m < 8; ++m)
                #pragma unroll
                for (int rp = 0; rp < 4; ++rp)
                    acc[m][rp] = add2(acc[m][rp],
                                      __shfl_xor_sync(0xFFFFFFFFu, acc[m][rp], s));
        }
        if (lane == 0) {
            #pragma unroll
            for (int m = 0; m < 8; ++m)
                #pragma unroll
                for (int rp = 0; rp < 4; ++rp)
                    part_s[kq][rg][m][rp] = acc[m][rp];
        }
    }
    __syncthreads();

    // combine 4 k-quarters -> t pairs (64 threads)
    if (tid < 64) {
        const int crg = tid >> 5;
        const int m   = (tid >> 2) & 7;
        const int rp  = tid & 3;
        const u64 s = add2(add2(part_s[0][crg][m][rp], part_s[1][crg][m][rp]),
                           add2(part_s[2][crg][m][rp], part_s[3][crg][m][rp]));
        const float2 f = unpack2(s);
        const int row = crg * 8 + m;
        const float tA = 2.0f * f.x;     // fold SCALING
        const float tB = 2.0f * f.y;
        t2_s[row][2 * rp + 0] = pack2(tA, tA);
        t2_s[row][2 * rp + 1] = pack2(tB, tB);
    }
    __syncthreads();

    // ---------------- Phase 2: out = t @ A ----------------
    #pragma unroll
    for (int j = 0; j < 4; ++j) {
        const int p = tid + j * TPB;                 // out float4 col (0..1023)
        u64 alo[RANK], ahi[RANK];
        #pragma unroll
        for (int r = 0; r < RANK; ++r) {
            const float4 a = A4[r * ND4 + p];
            alo[r] = pack2(a.x, a.y);
            ahi[r] = pack2(a.z, a.w);
        }

        #pragma unroll 4
        for (int m = 0; m < ROWS; ++m) {
            const ulonglong2* __restrict__ tp2 = (const ulonglong2*)t2_s[m];
            const ulonglong2 t01 = tp2[0];
            const ulonglong2 t23 = tp2[1];
            const ulonglong2 t45 = tp2[2];
            const ulonglong2 t67 = tp2[3];

            u64 olo = 0ull, ohi = 0ull;
            fma2(olo, t01.x, alo[0]);  fma2(ohi, t01.x, ahi[0]);
            fma2(olo, t01.y, alo[1]);  fma2(ohi, t01.y, ahi[1]);
            fma2(olo, t23.x, alo[2]);  fma2(ohi, t23.x, ahi[2]);
            fma2(olo, t23.y, alo[3]);  fma2(ohi, t23.y, ahi[3]);
            fma2(olo, t45.x, alo[4]);  fma2(ohi, t45.x, ahi[4]);
            fma2(olo, t45.y, alo[5]);  fma2(ohi, t45.y, ahi[5]);
            fma2(olo, t67.x, alo[6]);  fma2(ohi, t67.x, ahi[6]);
            fma2(olo, t67.y, alo[7]);  fma2(ohi, t67.y, ahi[7]);

            const float2 f0 = unpack2(olo);
            const float2 f1 = unpack2(ohi);
            __stcs(&out4[(row0 + m) * ND4 + p], make_float4(f0.x, f0.y, f1.x, f1.y));
        }
    }
}

extern "C" void kernel_launch(void* const* d_in, const int* in_sizes, int n_in,
                              void* d_out, int out_size)
{
    const float* x = (const float*)d_in[0];   // [4,4096,4096]
    const float* A = (const float*)d_in[1];   // [8,4096]
    const float* B = (const float*)d_in[2];   // [4096,8]
    float* out = (float*)d_out;               // [4,4096,4096] fp32

    const int total_rows = 4 * 4096;          // 16384
    dim3 grid(total_rows / ROWS);             // 1024
    lora_v6_kernel<<<grid, TPB>>>(x, A, B, out);
}

// round 7
// speedup vs baseline: 1.2487x; 1.0086x over previous
#include <cuda_runtime.h>

#define TPB   256
#define KDIM  4096
#define KD4   1024
#define ND4   1024
#define RANK  8
#define ROWS  8             // rows per CTA

typedef unsigned long long u64;

// Interleaved pack of B for perfectly-coalesced LDG.128:
// For each 32-wide p-block b (p = float4-k index), 512 u64 arranged as
// 8 segments of 64 u64: seg sub (= rp*2+pr) holds, at lane*2+j,
// {B[k][2rp], B[k][2rp+1]} for k = 4*(b*32+lane) + 2*pr + j.
__device__ u64 BX_g[4 * KDIM];   // 16384 u64 = 128 KB

__global__ void pack_BX_kernel(const float* __restrict__ B)
{
    const int o = blockIdx.x * blockDim.x + threadIdx.x;  // 0..16383, coalesced write
    const int b    = o >> 9;
    const int r    = o & 511;
    const int sub  = r >> 6;
    const int lane = (r & 63) >> 1;
    const int j    = r & 1;
    const int rp   = sub >> 1;
    const int pr   = sub & 1;
    const int k    = 4 * (b * 32 + lane) + 2 * pr + j;
    BX_g[o] = ((const u64*)B)[k * 4 + rp];
}

__device__ __forceinline__ u64 pack2(float lo, float hi) {
    u64 d; asm("mov.b64 %0, {%1,%2};" : "=l"(d) : "f"(lo), "f"(hi)); return d;
}
__device__ __forceinline__ void fma2(u64 &d, u64 a, u64 b) {
    asm("fma.rn.f32x2 %0, %1, %2, %0;" : "+l"(d) : "l"(a), "l"(b));
}
__device__ __forceinline__ u64 add2(u64 a, u64 b) {
    u64 d; asm("add.rn.f32x2 %0, %1, %2;" : "=l"(d) : "l"(a), "l"(b)); return d;
}
__device__ __forceinline__ float2 unpack2(u64 v) {
    float2 f; asm("mov.b64 {%0,%1}, %2;" : "=f"(f.x), "=f"(f.y) : "l"(v)); return f;
}

// Warp w = all 8 rows x k-eighth [w*512, (w+1)*512). grid 2048 -> ~7 waves.
__global__ __launch_bounds__(TPB, 2)
void lora_v7_kernel(const float* __restrict__ x,
                    const float* __restrict__ A,
                    float* __restrict__ out)
{
    __shared__ u64 part_s[8][ROWS][4];   // [kq][m][rp]
    __shared__ u64 t2_s[ROWS][RANK];     // {t,t} broadcast pairs

    const int tid  = threadIdx.x;
    const int lane = tid & 31;
    const int warp = tid >> 5;
    const size_t row0 = (size_t)blockIdx.x * ROWS;

    const float4* __restrict__ x4 = (const float4*)x;
    const float4* __restrict__ A4 = (const float4*)A;
    float4* __restrict__ out4 = (float4*)out;

    // ---------------- Phase 1: t = 2 * x @ B ----------------
    {
        const float4* __restrict__ xr = x4 + row0 * KD4;

        u64 acc[ROWS][4];
        #pragma unroll
        for (int m = 0; m < ROWS; ++m)
            #pragma unroll
            for (int rp = 0; rp < 4; ++rp) acc[m][rp] = 0ull;

        #pragma unroll 1
        for (int i = 0; i < 4; ++i) {
            const int p = warp * 128 + i * 32 + lane;   // float4-k index
            const int b = warp * 4 + i;                 // 32-p block

            // 8 perfectly-coalesced LDG.128 of B (4 lines each)
            const ulonglong2* __restrict__ bx =
                (const ulonglong2*)BX_g + (size_t)b * 256 + lane;
            ulonglong2 bp[8];
            #pragma unroll
            for (int sub = 0; sub < 8; ++sub)
                bp[sub] = bx[sub * 32];

            #pragma unroll
            for (int h = 0; h < 2; ++h) {
                float4 xv[4];
                #pragma unroll
                for (int q = 0; q < 4; ++q)
                    xv[q] = __ldcs(xr + (h * 4 + q) * KD4 + p);

                #pragma unroll
                for (int q = 0; q < 4; ++q) {
                    const int m = h * 4 + q;
                    const u64 xb0 = pack2(xv[q].x, xv[q].x);   // k=4p+0
                    const u64 xb1 = pack2(xv[q].y, xv[q].y);   // k=4p+1
                    const u64 xb2 = pack2(xv[q].z, xv[q].z);   // k=4p+2
                    const u64 xb3 = pack2(xv[q].w, xv[q].w);   // k=4p+3
                    #pragma unroll
                    for (int rp = 0; rp < 4; ++rp) {
                        // bp[2rp]   = {k=4p+0, k=4p+1} pairs for this rp
                        // bp[2rp+1] = {k=4p+2, k=4p+3}
                        fma2(acc[m][rp], xb0, bp[2 * rp].x);
                        fma2(acc[m][rp], xb1, bp[2 * rp].y);
                        fma2(acc[m][rp], xb2, bp[2 * rp + 1].x);
                        fma2(acc[m][rp], xb3, bp[2 * rp + 1].y);
                    }
                }
            }
        }

        #pragma unroll
        for (int s = 16; s; s >>= 1) {
            #pragma unroll
            for (int m = 0; m < ROWS; ++m)
                #pragma unroll
                for (int rp = 0; rp < 4; ++rp)
                    acc[m][rp] = add2(acc[m][rp],
                                      __shfl_xor_sync(0xFFFFFFFFu, acc[m][rp], s));
        }
        if (lane == 0) {
            #pragma unroll
            for (int m = 0; m < ROWS; ++m)
                #pragma unroll
                for (int rp = 0; rp < 4; ++rp)
                    part_s[warp][m][rp] = acc[m][rp];
        }
    }
    __syncthreads();

    // combine 8 k-eighths -> t pairs (32 threads)
    if (tid < 32) {
        const int m  = tid >> 2;
        const int rp = tid & 3;
        u64 s = part_s[0][m][rp];
        #pragma unroll
        for (int kq = 1; kq < 8; ++kq)
            s = add2(s, part_s[kq][m][rp]);
        const float2 f = unpack2(s);
        const float tA = 2.0f * f.x;     // fold SCALING
        const float tB = 2.0f * f.y;
        t2_s[m][2 * rp + 0] = pack2(tA, tA);
        t2_s[m][2 * rp + 1] = pack2(tB, tB);
    }
    __syncthreads();

    // ---------------- Phase 2: out = t @ A ----------------
    #pragma unroll
    for (int j = 0; j < 4; ++j) {
        const int p = tid + j * TPB;                 // out float4 col (0..1023)
        u64 alo[RANK], ahi[RANK];
        #pragma unroll
        for (int r = 0; r < RANK; ++r) {
            const float4 a = A4[r * ND4 + p];
            alo[r] = pack2(a.x, a.y);
            ahi[r] = pack2(a.z, a.w);
        }

        #pragma unroll
        for (int m = 0; m < ROWS; ++m) {
            const ulonglong2* __restrict__ tp2 = (const ulonglong2*)t2_s[m];
            const ulonglong2 t01 = tp2[0];
            const ulonglong2 t23 = tp2[1];
            const ulonglong2 t45 = tp2[2];
            const ulonglong2 t67 = tp2[3];

            u64 olo = 0ull, ohi = 0ull;
            fma2(olo, t01.x, alo[0]);  fma2(ohi, t01.x, ahi[0]);
            fma2(olo, t01.y, alo[1]);  fma2(ohi, t01.y, ahi[1]);
            fma2(olo, t23.x, alo[2]);  fma2(ohi, t23.x, ahi[2]);
            fma2(olo, t23.y, alo[3]);  fma2(ohi, t23.y, ahi[3]);
            fma2(olo, t45.x, alo[4]);  fma2(ohi, t45.x, ahi[4]);
            fma2(olo, t45.y, alo[5]);  fma2(ohi, t45.y, ahi[5]);
            fma2(olo, t67.x, alo[6]);  fma2(ohi, t67.x, ahi[6]);
            fma2(olo, t67.y, alo[7]);  fma2(ohi, t67.y, ahi[7]);

            const float2 f0 = unpack2(olo);
            const float2 f1 = unpack2(ohi);
            __stcs(&out4[(row0 + m) * ND4 + p], make_float4(f0.x, f0.y, f1.x, f1.y));
        }
    }
}

extern "C" void kernel_launch(void* const* d_in, const int* in_sizes, int n_in,
                              void* d_out, int out_size)
{
    const float* x = (const float*)d_in[0];   // [4,4096,4096]
    const float* A = (const float*)d_in[1];   // [8,4096]
    const float* B = (const float*)d_in[2];   // [4096,8]
    float* out = (float*)d_out;               // [4,4096,4096] fp32

    pack_BX_kernel<<<(4 * KDIM) / TPB, TPB>>>(B);

    const int total_rows = 4 * 4096;          // 16384
    dim3 grid(total_rows / ROWS);             // 2048
    lora_v7_kernel<<<grid, TPB>>>(x, A, out);
}

// round 8
// speedup vs baseline: 1.3133x; 1.0517x over previous
#include <cuda_runtime.h>

#define TPB   256
#define KDIM  4096
#define KD4   1024
#define ND4   1024
#define RANK  8

typedef unsigned long long u64;

// Interleaved pack of B for perfectly-coalesced LDG.128 (verified in R7):
// For each 32-wide p-block b (p = float4-k index), 512 u64 arranged as
// 8 segments of 64 u64: seg sub (= rp*2+pr) holds, at lane*2+j,
// {B[k][2rp], B[k][2rp+1]} for k = 4*(b*32+lane) + 2*pr + j.
__device__ u64 BX_g[4 * KDIM];            // 128 KB
__device__ float t_g[16384 * RANK];       // t = 2 * x @ B, 512 KB

__global__ void pack_BX_kernel(const float* __restrict__ B)
{
    const int o = blockIdx.x * blockDim.x + threadIdx.x;  // 0..16383
    const int b    = o >> 9;
    const int r    = o & 511;
    const int sub  = r >> 6;
    const int lane = (r & 63) >> 1;
    const int j    = r & 1;
    const int rp   = sub >> 1;
    const int pr   = sub & 1;
    const int k    = 4 * (b * 32 + lane) + 2 * pr + j;
    BX_g[o] = ((const u64*)B)[k * 4 + rp];
}

__device__ __forceinline__ u64 pack2(float lo, float hi) {
    u64 d; asm("mov.b64 %0, {%1,%2};" : "=l"(d) : "f"(lo), "f"(hi)); return d;
}
__device__ __forceinline__ void fma2(u64 &d, u64 a, u64 b) {
    asm("fma.rn.f32x2 %0, %1, %2, %0;" : "+l"(d) : "l"(a), "l"(b));
}
__device__ __forceinline__ u64 add2(u64 a, u64 b) {
    u64 d; asm("add.rn.f32x2 %0, %1, %2;" : "=l"(d) : "l"(a), "l"(b)); return d;
}
__device__ __forceinline__ float2 unpack2(u64 v) {
    float2 f; asm("mov.b64 {%0,%1}, %2;" : "=f"(f.x), "=f"(f.y) : "l"(v)); return f;
}

// ============ K1: t = 2 * x @ B  (pure read stream) ============
// 16 rows/CTA, grid 1024. Warp = 8 rows x 1024-k quarter (8 iters).
#define K1_ROWS 16

__global__ __launch_bounds__(TPB, 2)
void lora_k1_kernel(const float* __restrict__ x)
{
    __shared__ u64 part_s[4][K1_ROWS][4];   // [kq][row][rp]

    const int tid  = threadIdx.x;
    const int lane = tid & 31;
    const int warp = tid >> 5;
    const int rg   = warp & 1;              // row group (8 rows)
    const int kq   = warp >> 1;             // k quarter
    const size_t row0 = (size_t)blockIdx.x * K1_ROWS;

    const float4* __restrict__ xr = (const float4*)x + (row0 + rg * 8) * KD4;

    u64 acc[8][4];
    #pragma unroll
    for (int m = 0; m < 8; ++m)
        #pragma unroll
        for (int rp = 0; rp < 4; ++rp) acc[m][rp] = 0ull;

    #pragma unroll 1
    for (int i = 0; i < 8; ++i) {
        const int p = kq * 256 + i * 32 + lane;    // float4-k index
        const int b = kq * 8 + i;                  // 32-p block

        const ulonglong2* __restrict__ bx =
            (const ulonglong2*)BX_g + (size_t)b * 256 + lane;
        ulonglong2 bp[8];
        #pragma unroll
        for (int sub = 0; sub < 8; ++sub)
            bp[sub] = bx[sub * 32];

        #pragma unroll
        for (int h = 0; h < 2; ++h) {
            float4 xv[4];
            #pragma unroll
            for (int q = 0; q < 4; ++q)
                xv[q] = __ldcs(xr + (h * 4 + q) * KD4 + p);

            #pragma unroll
            for (int q = 0; q < 4; ++q) {
                const int m = h * 4 + q;
                const u64 xb0 = pack2(xv[q].x, xv[q].x);
                const u64 xb1 = pack2(xv[q].y, xv[q].y);
                const u64 xb2 = pack2(xv[q].z, xv[q].z);
                const u64 xb3 = pack2(xv[q].w, xv[q].w);
                #pragma unroll
                for (int rp = 0; rp < 4; ++rp) {
                    fma2(acc[m][rp], xb0, bp[2 * rp].x);
                    fma2(acc[m][rp], xb1, bp[2 * rp].y);
                    fma2(acc[m][rp], xb2, bp[2 * rp + 1].x);
                    fma2(acc[m][rp], xb3, bp[2 * rp + 1].y);
                }
            }
        }
    }

    #pragma unroll
    for (int s = 16; s; s >>= 1) {
        #pragma unroll
        for (int m = 0; m < 8; ++m)
            #pragma unroll
            for (int rp = 0; rp < 4; ++rp)
                acc[m][rp] = add2(acc[m][rp],
                                  __shfl_xor_sync(0xFFFFFFFFu, acc[m][rp], s));
    }
    if (lane == 0) {
        #pragma unroll
        for (int m = 0; m < 8; ++m)
            #pragma unroll
            for (int rp = 0; rp < 4; ++rp)
                part_s[kq][rg * 8 + m][rp] = acc[m][rp];
    }
    __syncthreads();

    // combine 4 k-quarters -> t  (64 threads, float2 stores)
    if (tid < 64) {
        const int row = tid >> 2;
        const int rp  = tid & 3;
        const u64 s = add2(add2(part_s[0][row][rp], part_s[1][row][rp]),
                           add2(part_s[2][row][rp], part_s[3][row][rp]));
        const float2 f = unpack2(s);
        float2* __restrict__ t2 = (float2*)t_g;
        t2[(row0 + row) * 4 + rp] = make_float2(2.0f * f.x, 2.0f * f.y);
    }
}

// ============ K2: out = t @ A  (pure write stream) ============
// CTA = 32 rows x 256 f4-columns quarter. grid 2048 (colq inner).
#define K2_ROWS 32

__global__ __launch_bounds__(TPB)
void lora_k2_kernel(const float* __restrict__ A, float* __restrict__ out)
{
    __shared__ u64 t2_s[K2_ROWS][RANK];     // {t,t} broadcast pairs

    const int tid  = threadIdx.x;
    const int colq = blockIdx.x & 3;
    const size_t row0 = (size_t)(blockIdx.x >> 2) * K2_ROWS;

    // 256 threads load exactly 32x8 t values
    {
        const float v = t_g[row0 * RANK + tid];
        t2_s[tid >> 3][tid & 7] = pack2(v, v);
    }
    __syncthreads();

    const int p = colq * 256 + tid;          // this thread's single f4 column
    const float4* __restrict__ A4 = (const float4*)A;
    float4* __restrict__ out4 = (float4*)out;

    u64 alo[RANK], ahi[RANK];
    #pragma unroll
    for (int r = 0; r < RANK; ++r) {
        const float4 a = A4[r * ND4 + p];
        alo[r] = pack2(a.x, a.y);
        ahi[r] = pack2(a.z, a.w);
    }

    #pragma unroll 4
    for (int m = 0; m < K2_ROWS; ++m) {
        const ulonglong2* __restrict__ tp2 = (const ulonglong2*)t2_s[m];
        const ulonglong2 t01 = tp2[0];
        const ulonglong2 t23 = tp2[1];
        const ulonglong2 t45 = tp2[2];
        const ulonglong2 t67 = tp2[3];

        u64 olo = 0ull, ohi = 0ull;
        fma2(olo, t01.x, alo[0]);  fma2(ohi, t01.x, ahi[0]);
        fma2(olo, t01.y, alo[1]);  fma2(ohi, t01.y, ahi[1]);
        fma2(olo, t23.x, alo[2]);  fma2(ohi, t23.x, ahi[2]);
        fma2(olo, t23.y, alo[3]);  fma2(ohi, t23.y, ahi[3]);
        fma2(olo, t45.x, alo[4]);  fma2(ohi, t45.x, ahi[4]);
        fma2(olo, t45.y, alo[5]);  fma2(ohi, t45.y, ahi[5]);
        fma2(olo, t67.x, alo[6]);  fma2(ohi, t67.x, ahi[6]);
        fma2(olo, t67.y, alo[7]);  fma2(ohi, t67.y, ahi[7]);

        const float2 f0 = unpack2(olo);
        const float2 f1 = unpack2(ohi);
        __stcs(&out4[(row0 + m) * ND4 + p], make_float4(f0.x, f0.y, f1.x, f1.y));
    }
}

extern "C" void kernel_launch(void* const* d_in, const int* in_sizes, int n_in,
                              void* d_out, int out_size)
{
    const float* x = (const float*)d_in[0];   // [4,4096,4096]
    const float* A = (const float*)d_in[1];   // [8,4096]
    const float* B = (const float*)d_in[2];   // [4096,8]
    float* out = (float*)d_out;               // [4,4096,4096] fp32

    pack_BX_kernel<<<(4 * KDIM) / TPB, TPB>>>(B);

    lora_k1_kernel<<<16384 / K1_ROWS, TPB>>>(x);                 // grid 1024
    lora_k2_kernel<<<(16384 / K2_ROWS) * 4, TPB>>>(A, out);      // grid 2048
}